// round 12
// baseline (speedup 1.0000x reference)
#include <cuda_runtime.h>
#include <cuda_fp16.h>
#include <cstdint>

#define E_NUM 32
#define DK 1024
#define DN 1024
#define BM 128
#define BN 128
#define KC 64            /* fp16 per K-chunk = 128 bytes/row */
#define NCHUNK (DK / KC) /* 16 */
#define STAGES 3
#define MT_CAP 1152
#define TMAX 131072LL
#define PGRID 304        /* persistent grid: 2 CTAs x 152 SMs */

/* ---------------- scratch (device globals; no allocation APIs) -------------- */
static __device__ __align__(1024) __half g_Ah[TMAX * DK];                   /* 256 MB */
static __device__ __align__(1024) __half g_Wh[(long long)E_NUM * DN * DK];  /* 64 MB  */
static __device__ int g_tile_expert[MT_CAP];
static __device__ int g_tile_row[MT_CAP];
static __device__ int g_tile_nrows[MT_CAP];
static __device__ int g_num_mtiles;

/* ---------------- helpers ---------------- */
static __device__ __forceinline__ uint32_t smem_u32(const void* p) {
    uint32_t a;
    asm("{ .reg .u64 t; cvta.to.shared.u64 t, %1; cvt.u32.u64 %0, t; }" : "=r"(a) : "l"(p));
    return a;
}
static __device__ __forceinline__ void cp16(uint32_t dst, const void* src, int src_size) {
    asm volatile("cp.async.cg.shared.global [%0], [%1], 16, %2;\n"
                 :: "r"(dst), "l"(src), "r"(src_size));
}
static __device__ __forceinline__ void cp_async_arrive(uint32_t mbar) {
    asm volatile("cp.async.mbarrier.arrive.noinc.shared.b64 [%0];" :: "r"(mbar) : "memory");
}

#define MBARRIER_INIT(addr, cnt) \
    asm volatile("mbarrier.init.shared.b64 [%0], %1;" :: "r"((uint32_t)(addr)), "r"((uint32_t)(cnt)) : "memory")
#define MBARRIER_ARRIVE(addr) \
    asm volatile("mbarrier.arrive.shared.b64 _, [%0];" :: "r"((uint32_t)(addr)) : "memory")

/* acquire wait: consumer side (generic-proxy LDS reads follow) */
#define MBARRIER_WAIT_PARITY(mbar_smem_addr, phase_parity) do {                                   \
    uint32_t _mbar = (uint32_t)(mbar_smem_addr);                                                  \
    uint32_t _parity = (uint32_t)(phase_parity);                                                  \
    uint32_t _done;                                                                               \
    asm volatile(                                                                                 \
        "{\n\t"                                                                                   \
        ".reg .pred p;\n\t"                                                                       \
        "mbarrier.try_wait.parity.acquire.cta.shared::cta.b64 p, [%1], %2;\n\t"                   \
        "selp.b32 %0, 1, 0, p;\n\t"                                                               \
        "}"                                                                                       \
        : "=r"(_done) : "r"(_mbar), "r"(_parity) : "memory");                                     \
    if (!_done) {                                                                                 \
        asm volatile(                                                                             \
            "{\n\t"                                                                               \
            ".reg .pred P1;\n\t"                                                                  \
            "WAIT_LOOP_%=:\n\t"                                                                   \
            "mbarrier.try_wait.parity.acquire.cta.shared::cta.b64 P1, [%0], %1, 0x989680;\n\t"    \
            "@P1 bra.uni WAIT_DONE_%=;\n\t"                                                       \
            "bra.uni WAIT_LOOP_%=;\n\t"                                                           \
            "WAIT_DONE_%=:\n\t"                                                                   \
            "}"                                                                                   \
            :: "r"(_mbar), "r"(_parity) : "memory");                                              \
    }                                                                                             \
} while (0)

/* relaxed wait: producer side (only async-proxy cp.async writes follow) */
#define MBARRIER_WAIT_PARITY_RELAXED(mbar_smem_addr, phase_parity) do {                           \
    uint32_t _mbar = (uint32_t)(mbar_smem_addr);                                                  \
    uint32_t _parity = (uint32_t)(phase_parity);                                                  \
    uint32_t _done;                                                                               \
    asm volatile(                                                                                 \
        "{\n\t"                                                                                   \
        ".reg .pred p;\n\t"                                                                       \
        "mbarrier.try_wait.parity.relaxed.cta.shared::cta.b64 p, [%1], %2;\n\t"                   \
        "selp.b32 %0, 1, 0, p;\n\t"                                                               \
        "}"                                                                                       \
        : "=r"(_done) : "r"(_mbar), "r"(_parity) : "memory");                                     \
    if (!_done) {                                                                                 \
        asm volatile(                                                                             \
            "{\n\t"                                                                               \
            ".reg .pred P1;\n\t"                                                                  \
            "WAIT_LOOP_%=:\n\t"                                                                   \
            "mbarrier.try_wait.parity.relaxed.cta.shared::cta.b64 P1, [%0], %1, 0x989680;\n\t"    \
            "@P1 bra.uni WAIT_DONE_%=;\n\t"                                                       \
            "bra.uni WAIT_LOOP_%=;\n\t"                                                           \
            "WAIT_DONE_%=:\n\t"                                                                   \
            "}"                                                                                   \
            :: "r"(_mbar), "r"(_parity) : "memory");                                              \
    }                                                                                             \
} while (0)

#define LDSM_X4(r0, r1, r2, r3, addr) \
    asm volatile("ldmatrix.sync.aligned.m8n8.x4.shared.b16 {%0,%1,%2,%3}, [%4];" \
                 : "=r"(r0), "=r"(r1), "=r"(r2), "=r"(r3) : "r"(addr))

#define MMA16816(c0, c1, c2, c3, a0, a1, a2, a3, b0, b1) \
    asm volatile("mma.sync.aligned.m16n8k16.row.col.f32.f16.f16.f32 " \
                 "{%0,%1,%2,%3}, {%4,%5,%6,%7}, {%8,%9}, {%0,%1,%2,%3};" \
                 : "+f"(c0), "+f"(c1), "+f"(c2), "+f"(c3) \
                 : "r"(a0), "r"(a1), "r"(a2), "r"(a3), "r"(b0), "r"(b1))

#define STG2_CS(ptr, vx, vy) \
    asm volatile("st.global.cs.v2.f32 [%0], {%1,%2};" :: "l"(ptr), "f"(vx), "f"(vy) : "memory")

/* -------- fused fp32->fp16 conversion (32B/thread-iter, evict-first reads)
   + integrated tile-table build in the LAST block.                          -- */
__global__ void cvt_all_kernel(const float4* __restrict__ srcW,
                               const float4* __restrict__ srcA,
                               long long nW16, long long nA16,
                               const int* __restrict__ ef, int T_tokens) {
    if (blockIdx.x == gridDim.x - 1) {
        if (threadIdx.x == 0) {
            long long s = 0;
            for (int i = 0; i < E_NUM; i++) s += ef[i];
            bool is64 = (s != (long long)T_tokens);
            long long off = 0;
            int t = 0;
            for (int e = 0; e < E_NUM; e++) {
                long long c;
                if (is64)
                    c = (long long)(unsigned)ef[2 * e] | ((long long)ef[2 * e + 1] << 32);
                else
                    c = ef[e];
                for (long long m = 0; m < c; m += BM) {
                    long long rem = c - m;
                    g_tile_expert[t] = e;
                    g_tile_row[t]    = (int)(off + m);
                    g_tile_nrows[t]  = (int)(rem < BM ? rem : BM);
                    t++;
                }
                off += c;
            }
            g_num_mtiles = t;
        }
        return;
    }

    const long long nbulk = (long long)(gridDim.x - 1) * blockDim.x;
    long long i = (long long)blockIdx.x * blockDim.x + threadIdx.x;
    uint4* dstW = reinterpret_cast<uint4*>(g_Wh);
    uint4* dstA = reinterpret_cast<uint4*>(g_Ah);
    const long long ntot = nW16 + nA16;
    for (; i < ntot; i += nbulk) {
        const bool isW = (i < nW16);
        const long long j = isW ? i : (i - nW16);
        const float4* s = isW ? (srcW + 4 * j) : (srcA + 4 * j);
        float4 v0 = __ldcs(s + 0);
        float4 v1 = __ldcs(s + 1);
        float4 v2 = __ldcs(s + 2);
        float4 v3 = __ldcs(s + 3);
        __half2 h;
        uint4 u0, u1;
        h = __floats2half2_rn(v0.x, v0.y); u0.x = *(uint32_t*)&h;
        h = __floats2half2_rn(v0.z, v0.w); u0.y = *(uint32_t*)&h;
        h = __floats2half2_rn(v1.x, v1.y); u0.z = *(uint32_t*)&h;
        h = __floats2half2_rn(v1.z, v1.w); u0.w = *(uint32_t*)&h;
        h = __floats2half2_rn(v2.x, v2.y); u1.x = *(uint32_t*)&h;
        h = __floats2half2_rn(v2.z, v2.w); u1.y = *(uint32_t*)&h;
        h = __floats2half2_rn(v3.x, v3.y); u1.z = *(uint32_t*)&h;
        h = __floats2half2_rn(v3.z, v3.w); u1.w = *(uint32_t*)&h;
        if (isW) { dstW[2 * j] = u0; dstW[2 * j + 1] = u1; }
        else     { dstA[2 * j] = u0; dstA[2 * j + 1] = u1; }
    }
}

/* ---------------- persistent grouped-GEMM kernel (mma.sync fp16) -----------
   CTA 128x128, 8 warps (4m x 2n), warp 32x64, 3-stage mbarrier pipeline
   (early release + relaxed producer waits), 2 CTAs/SM. PERSISTENT: 304 CTAs
   loop over tiles; the pipeline continues across tile boundaries (chunks
   14/15 of tile i produce chunks 0/1 of tile i+GRID), overlapping the next
   tile's loads with this tile's tail MMAs and epilogue. Epilogue stores are
   streaming (st.global.cs).                                                  */

#define STAGE_BYTES 32768              /* A 16KB + B 16KB */
#define MBAR_BYTES  1024
#define SMEM_TOTAL  (STAGES * STAGE_BYTES + MBAR_BYTES)
/* mbar layout: full[s] at +s*8; empty[s] at +32+s*8 */

static __device__ __forceinline__ void produce_chunk_p(
    int slot, int gp, int cc, uint32_t smem_base, uint32_t mbar_base,
    const __half* __restrict__ gA, const __half* __restrict__ gB,
    int a_sz, int tid, uint32_t* emptyph)
{
    if (gp >= STAGES) {   /* first use of each physical stage needs no wait */
        MBARRIER_WAIT_PARITY_RELAXED(mbar_base + 32 + slot * 8, (*emptyph >> slot) & 1);
        *emptyph ^= (1u << slot);
    }
    const int row  = tid >> 1;
    const int j0   = (tid & 1) * 4;
    const uint32_t xorv = (uint32_t)(row & 7) * 16u;
    uint32_t sA = smem_base + (uint32_t)slot * STAGE_BYTES + (uint32_t)row * 128u;
    uint32_t sB = sA + 16384u;
    const char* srcA = (const char*)(gA + (size_t)row * DK + (size_t)cc * KC) + j0 * 16;
    const char* srcB = (const char*)(gB + (size_t)row * DK + (size_t)cc * KC) + j0 * 16;
#pragma unroll
    for (int j = 0; j < 4; j++) {
        uint32_t col = ((uint32_t)(j0 + j) * 16u) ^ xorv;
        cp16(sA + col, srcA + j * 16, a_sz);
        cp16(sB + col, srcB + j * 16, 16);
    }
    cp_async_arrive(mbar_base + slot * 8);
}

__global__ void __launch_bounds__(256, 2) gemm_kernel(
    const float* __restrict__ bias, float* __restrict__ out, int T_tokens)
{
    extern __shared__ __align__(1024) char smem[];
    const int GRID  = gridDim.x;
    const int total = g_num_mtiles << 3;          /* tiles: t = mt*8 + nt */
    int t = blockIdx.x;
    if (t >= total) return;

    const uint32_t smem_base = smem_u32(smem);
    const uint32_t mbar_base = smem_base + STAGES * STAGE_BYTES;
    const int tid  = threadIdx.x;
    const int lane = tid & 31;
    const int wid  = tid >> 5;
    const int warp_m = wid >> 1;
    const int warp_n = wid & 1;

    if (tid == 0) {
#pragma unroll
        for (int s = 0; s < STAGES; s++) {
            MBARRIER_INIT(mbar_base + s * 8, 256);       /* full  */
            MBARRIER_INIT(mbar_base + 32 + s * 8, 8);    /* empty */
        }
    }
    __syncthreads();

    /* ldmatrix per-lane address components (tile-invariant) */
    uint32_t aRow[2], aXor[2];
#pragma unroll
    for (int mf = 0; mf < 2; mf++) {
        int r = warp_m * 32 + mf * 16 + (lane & 15);
        aRow[mf] = (uint32_t)r * 128u;
        aXor[mf] = (uint32_t)(r & 7) * 16u;
    }
    const uint32_t aHi = (uint32_t)((lane >> 4) & 1) * 16u;

    uint32_t bRow[4], bXor[4];
#pragma unroll
    for (int g = 0; g < 4; g++) {
        int r = warp_n * 64 + g * 16 + (lane & 7) + (((lane >> 4) & 1) << 3);
        bRow[g] = (uint32_t)r * 128u;
        bXor[g] = (uint32_t)(r & 7) * 16u;
    }
    const uint32_t bHi = (uint32_t)((lane >> 3) & 1) * 16u;

    /* producer-side tile pointers (current produce target) */
    const __half *pA, *pB;
    int p_asz;
    {
        const int mt = t >> 3, nt0 = t & 7;
        const int e = g_tile_expert[mt], row0 = g_tile_row[mt];
        pA = g_Ah + (size_t)row0 * DK;
        pB = g_Wh + ((size_t)e * DN + (size_t)nt0 * BN) * DK;
        p_asz = (row0 + (tid >> 1) < T_tokens) ? 16 : 0;
    }

    uint32_t fullph = 0, emptyph = 0;
    int pslot = 0, cslot = 0;
    int gp = 0;                                   /* global produced-chunk count */

    /* prologue: chunks 0,1 of first tile */
    produce_chunk_p(0, gp, 0, smem_base, mbar_base, pA, pB, p_asz, tid, &emptyph); gp++;
    produce_chunk_p(1, gp, 1, smem_base, mbar_base, pA, pB, p_asz, tid, &emptyph); gp++;
    pslot = 2;

#pragma unroll 1
    for (; t < total; t += GRID) {
        const int mt = t >> 3, ntc = t & 7;
        const int e     = g_tile_expert[mt];
        const int row0  = g_tile_row[mt];
        const int nrows = g_tile_nrows[mt];
        const bool hasNext = (t + GRID) < total;

        /* warm L2 with this tile's bias segment */
        const float* bseg = bias + (size_t)e * DN + (size_t)ntc * BN;
        if (tid < 4)
            asm volatile("prefetch.global.L2 [%0];" :: "l"(bseg + tid * 32));

        float acc[2][8][4];
#pragma unroll
        for (int mf = 0; mf < 2; mf++)
#pragma unroll
            for (int nf = 0; nf < 8; nf++)
#pragma unroll
                for (int k = 0; k < 4; k++) acc[mf][nf][k] = 0.0f;

#pragma unroll 1
        for (int c = 0; c < NCHUNK; c++) {
            /* ---- produce chunk c+2 (this tile, or chunks 0/1 of next) ---- */
            const int q = c + 2;
            if (q < NCHUNK) {
                produce_chunk_p(pslot, gp, q, smem_base, mbar_base, pA, pB, p_asz, tid, &emptyph);
                pslot = (pslot == STAGES - 1) ? 0 : pslot + 1;
                gp++;
            } else if (hasNext) {
                if (q == NCHUNK) {   /* switch producer pointers to next tile */
                    const int t2 = t + GRID;
                    const int mt2 = t2 >> 3, nt2 = t2 & 7;
                    const int e2 = g_tile_expert[mt2], r2 = g_tile_row[mt2];
                    pA = g_Ah + (size_t)r2 * DK;
                    pB = g_Wh + ((size_t)e2 * DN + (size_t)nt2 * BN) * DK;
                    p_asz = (r2 + (tid >> 1) < T_tokens) ? 16 : 0;
                }
                produce_chunk_p(pslot, gp, q - NCHUNK, smem_base, mbar_base, pA, pB, p_asz, tid, &emptyph);
                pslot = (pslot == STAGES - 1) ? 0 : pslot + 1;
                gp++;
            }

            /* ---- consume chunk c ---- */
            MBARRIER_WAIT_PARITY(mbar_base + cslot * 8, (fullph >> cslot) & 1);
            fullph ^= (1u << cslot);

            const uint32_t sA = smem_base + (uint32_t)cslot * STAGE_BYTES;
            const uint32_t sB = sA + 16384u;

#pragma unroll
            for (int ks = 0; ks < 4; ks++) {
                const uint32_t kb = (uint32_t)ks * 32u;
                uint32_t a[2][4];
#pragma unroll
                for (int mf = 0; mf < 2; mf++) {
                    uint32_t addr = sA + aRow[mf] + ((kb + aHi) ^ aXor[mf]);
                    LDSM_X4(a[mf][0], a[mf][1], a[mf][2], a[mf][3], addr);
                }
                uint32_t b[4][4];
#pragma unroll
                for (int g = 0; g < 4; g++) {
                    uint32_t addr = sB + bRow[g] + ((kb + bHi) ^ bXor[g]);
                    LDSM_X4(b[g][0], b[g][1], b[g][2], b[g][3], addr);
                }

                /* after the last ks's LDSMs this warp is done with the stage */
                if (ks == 3 && lane == 0) MBARRIER_ARRIVE(mbar_base + 32 + cslot * 8);

#pragma unroll
                for (int mf = 0; mf < 2; mf++) {
#pragma unroll
                    for (int nf = 0; nf < 8; nf++) {
                        const int g  = nf >> 1;
                        const int hi = (nf & 1) * 2;
                        MMA16816(acc[mf][nf][0], acc[mf][nf][1], acc[mf][nf][2], acc[mf][nf][3],
                                 a[mf][0], a[mf][1], a[mf][2], a[mf][3],
                                 b[g][hi], b[g][hi + 1]);
                    }
                }
            }
            cslot = (cslot == STAGES - 1) ? 0 : cslot + 1;
        }

        /* ---- epilogue: out = acc + bias (streaming stores) ----
           next tile's chunks 0/1 are already in flight underneath this     */
        const int colBase = ntc * BN + warp_n * 64 + (lane & 3) * 2;
        const float* brow = bias + (size_t)e * DN;
#pragma unroll
        for (int mf = 0; mf < 2; mf++) {
#pragma unroll
            for (int half = 0; half < 2; half++) {
                const int r = warp_m * 32 + mf * 16 + (lane >> 2) + half * 8;
                if (r < nrows) {
                    float* orow = out + (size_t)(row0 + r) * DN;
#pragma unroll
                    for (int nf = 0; nf < 8; nf++) {
                        const int col = colBase + nf * 8;
                        float vx = acc[mf][nf][half * 2 + 0] + brow[col];
                        float vy = acc[mf][nf][half * 2 + 1] + brow[col + 1];
                        STG2_CS(orow + col, vx, vy);
                    }
                }
            }
        }
    }
}

/* ---------------- host launcher ---------------- */
extern "C" void kernel_launch(void* const* d_in, const int* in_sizes, int n_in,
                              void* d_out, int out_size)
{
    const float* x    = (const float*)d_in[0];
    const int*   ef   = (const int*)d_in[1];
    const float* w    = (const float*)d_in[2];
    const float* bias = (const float*)d_in[3];
    float* out = (float*)d_out;

    const long long T = (long long)in_sizes[0] / DK;

    const long long nA16 = T * DK / 16;
    const long long nW16 = (long long)E_NUM * DN * DK / 16;
    cvt_all_kernel<<<4737, 256>>>((const float4*)w, (const float4*)x, nW16, nA16,
                                  ef, (int)T);

    cudaFuncSetAttribute(gemm_kernel, cudaFuncAttributeMaxDynamicSharedMemorySize, SMEM_TOTAL);

    gemm_kernel<<<PGRID, 256, SMEM_TOTAL>>>(bias, out, (int)T);
}

// round 13
// speedup vs baseline: 1.0103x; 1.0103x over previous
#include <cuda_runtime.h>
#include <cuda_fp16.h>
#include <cstdint>

#define E_NUM 32
#define DK 1024
#define DN 1024
#define BM 128
#define BN 128
#define KC 64            /* fp16 per K-chunk = 128 bytes/row */
#define NCHUNK (DK / KC) /* 16 */
#define STAGES 3
#define MT_CAP 1152
#define TMAX 131072LL

/* ---------------- scratch (device globals; no allocation APIs) -------------- */
static __device__ __align__(1024) __half g_Ah[TMAX * DK];                   /* 256 MB */
static __device__ __align__(1024) __half g_Wh[(long long)E_NUM * DN * DK];  /* 64 MB  */
static __device__ int g_tile_expert[MT_CAP];
static __device__ int g_tile_row[MT_CAP];
static __device__ int g_tile_nrows[MT_CAP];
static __device__ int g_num_mtiles;

/* ---------------- helpers ---------------- */
static __device__ __forceinline__ uint32_t smem_u32(const void* p) {
    uint32_t a;
    asm("{ .reg .u64 t; cvta.to.shared.u64 t, %1; cvt.u32.u64 %0, t; }" : "=r"(a) : "l"(p));
    return a;
}
static __device__ __forceinline__ void cp16(uint32_t dst, const void* src, int src_size) {
    asm volatile("cp.async.cg.shared.global [%0], [%1], 16, %2;\n"
                 :: "r"(dst), "l"(src), "r"(src_size));
}
static __device__ __forceinline__ void cp_async_arrive(uint32_t mbar) {
    asm volatile("cp.async.mbarrier.arrive.noinc.shared.b64 [%0];" :: "r"(mbar) : "memory");
}

#define MBARRIER_INIT(addr, cnt) \
    asm volatile("mbarrier.init.shared.b64 [%0], %1;" :: "r"((uint32_t)(addr)), "r"((uint32_t)(cnt)) : "memory")
#define MBARRIER_ARRIVE(addr) \
    asm volatile("mbarrier.arrive.shared.b64 _, [%0];" :: "r"((uint32_t)(addr)) : "memory")

/* acquire wait: consumer side (generic-proxy LDS reads follow) */
#define MBARRIER_WAIT_PARITY(mbar_smem_addr, phase_parity) do {                                   \
    uint32_t _mbar = (uint32_t)(mbar_smem_addr);                                                  \
    uint32_t _parity = (uint32_t)(phase_parity);                                                  \
    uint32_t _done;                                                                               \
    asm volatile(                                                                                 \
        "{\n\t"                                                                                   \
        ".reg .pred p;\n\t"                                                                       \
        "mbarrier.try_wait.parity.acquire.cta.shared::cta.b64 p, [%1], %2;\n\t"                   \
        "selp.b32 %0, 1, 0, p;\n\t"                                                               \
        "}"                                                                                       \
        : "=r"(_done) : "r"(_mbar), "r"(_parity) : "memory");                                     \
    if (!_done) {                                                                                 \
        asm volatile(                                                                             \
            "{\n\t"                                                                               \
            ".reg .pred P1;\n\t"                                                                  \
            "WAIT_LOOP_%=:\n\t"                                                                   \
            "mbarrier.try_wait.parity.acquire.cta.shared::cta.b64 P1, [%0], %1, 0x989680;\n\t"    \
            "@P1 bra.uni WAIT_DONE_%=;\n\t"                                                       \
            "bra.uni WAIT_LOOP_%=;\n\t"                                                           \
            "WAIT_DONE_%=:\n\t"                                                                   \
            "}"                                                                                   \
            :: "r"(_mbar), "r"(_parity) : "memory");                                              \
    }                                                                                             \
} while (0)

/* relaxed wait: producer side (only async-proxy cp.async writes follow) */
#define MBARRIER_WAIT_PARITY_RELAXED(mbar_smem_addr, phase_parity) do {                           \
    uint32_t _mbar = (uint32_t)(mbar_smem_addr);                                                  \
    uint32_t _parity = (uint32_t)(phase_parity);                                                  \
    uint32_t _done;                                                                               \
    asm volatile(                                                                                 \
        "{\n\t"                                                                                   \
        ".reg .pred p;\n\t"                                                                       \
        "mbarrier.try_wait.parity.relaxed.cta.shared::cta.b64 p, [%1], %2;\n\t"                   \
        "selp.b32 %0, 1, 0, p;\n\t"                                                               \
        "}"                                                                                       \
        : "=r"(_done) : "r"(_mbar), "r"(_parity) : "memory");                                     \
    if (!_done) {                                                                                 \
        asm volatile(                                                                             \
            "{\n\t"                                                                               \
            ".reg .pred P1;\n\t"                                                                  \
            "WAIT_LOOP_%=:\n\t"                                                                   \
            "mbarrier.try_wait.parity.relaxed.cta.shared::cta.b64 P1, [%0], %1, 0x989680;\n\t"    \
            "@P1 bra.uni WAIT_DONE_%=;\n\t"                                                       \
            "bra.uni WAIT_LOOP_%=;\n\t"                                                           \
            "WAIT_DONE_%=:\n\t"                                                                   \
            "}"                                                                                   \
            :: "r"(_mbar), "r"(_parity) : "memory");                                              \
    }                                                                                             \
} while (0)

#define LDSM_X4(r0, r1, r2, r3, addr) \
    asm volatile("ldmatrix.sync.aligned.m8n8.x4.shared.b16 {%0,%1,%2,%3}, [%4];" \
                 : "=r"(r0), "=r"(r1), "=r"(r2), "=r"(r3) : "r"(addr))

#define MMA16816(c0, c1, c2, c3, a0, a1, a2, a3, b0, b1) \
    asm volatile("mma.sync.aligned.m16n8k16.row.col.f32.f16.f16.f32 " \
                 "{%0,%1,%2,%3}, {%4,%5,%6,%7}, {%8,%9}, {%0,%1,%2,%3};" \
                 : "+f"(c0), "+f"(c1), "+f"(c2), "+f"(c3) \
                 : "r"(a0), "r"(a1), "r"(a2), "r"(a3), "r"(b0), "r"(b1))

#define STG2_CS(ptr, vx, vy) \
    asm volatile("st.global.cs.v2.f32 [%0], {%1,%2};" :: "l"(ptr), "f"(vx), "f"(vy) : "memory")

/* -------- fused fp32->fp16 conversion (32B/thread-iter, evict-first reads)
   + integrated tile-table build: the LAST block builds the tile table while
   the remaining gridDim.x-1 blocks do the bulk conversion.                  -- */
__global__ void cvt_all_kernel(const float4* __restrict__ srcW,
                               const float4* __restrict__ srcA,
                               long long nW16, long long nA16,
                               const int* __restrict__ ef, int T_tokens) {
    if (blockIdx.x == gridDim.x - 1) {
        /* tile-table block: thread 0 builds; handles int32 OR int64 ef */
        if (threadIdx.x == 0) {
            long long s = 0;
            for (int i = 0; i < E_NUM; i++) s += ef[i];
            bool is64 = (s != (long long)T_tokens);
            long long off = 0;
            int t = 0;
            for (int e = 0; e < E_NUM; e++) {
                long long c;
                if (is64)
                    c = (long long)(unsigned)ef[2 * e] | ((long long)ef[2 * e + 1] << 32);
                else
                    c = ef[e];
                for (long long m = 0; m < c; m += BM) {
                    long long rem = c - m;
                    g_tile_expert[t] = e;
                    g_tile_row[t]    = (int)(off + m);
                    g_tile_nrows[t]  = (int)(rem < BM ? rem : BM);
                    t++;
                }
                off += c;
            }
            g_num_mtiles = t;
        }
        return;
    }

    const long long nbulk = (long long)(gridDim.x - 1) * blockDim.x;
    long long i = (long long)blockIdx.x * blockDim.x + threadIdx.x;
    uint4* dstW = reinterpret_cast<uint4*>(g_Wh);
    uint4* dstA = reinterpret_cast<uint4*>(g_Ah);
    const long long ntot = nW16 + nA16;
    for (; i < ntot; i += nbulk) {
        const bool isW = (i < nW16);
        const long long j = isW ? i : (i - nW16);
        const float4* s = isW ? (srcW + 4 * j) : (srcA + 4 * j);
        /* single-use streaming reads: evict-first */
        float4 v0 = __ldcs(s + 0);
        float4 v1 = __ldcs(s + 1);
        float4 v2 = __ldcs(s + 2);
        float4 v3 = __ldcs(s + 3);
        __half2 h;
        uint4 u0, u1;
        h = __floats2half2_rn(v0.x, v0.y); u0.x = *(uint32_t*)&h;
        h = __floats2half2_rn(v0.z, v0.w); u0.y = *(uint32_t*)&h;
        h = __floats2half2_rn(v1.x, v1.y); u0.z = *(uint32_t*)&h;
        h = __floats2half2_rn(v1.z, v1.w); u0.w = *(uint32_t*)&h;
        h = __floats2half2_rn(v2.x, v2.y); u1.x = *(uint32_t*)&h;
        h = __floats2half2_rn(v2.z, v2.w); u1.y = *(uint32_t*)&h;
        h = __floats2half2_rn(v3.x, v3.y); u1.z = *(uint32_t*)&h;
        h = __floats2half2_rn(v3.z, v3.w); u1.w = *(uint32_t*)&h;
        if (isW) { dstW[2 * j] = u0; dstW[2 * j + 1] = u1; }
        else     { dstA[2 * j] = u0; dstA[2 * j + 1] = u1; }
    }
}

/* ---------------- main grouped-GEMM kernel (mma.sync fp16) ----------------
   R11 config (best): CTA 128x128, 8 warps (4m x 2n), warp 32x64, K-chunk 64,
   3-stage mbarrier full/empty pipeline, early empty release after last
   LDSMs, relaxed producer waits, bias L2 prefetch, 2 CTAs/SM.
   NEW vs R11: epilogue stores are streaming (st.global.cs) — output is
   write-once, so evict early and keep L2 for the A/B reuse stream.           */

#define STAGE_BYTES 32768              /* A 16KB + B 16KB */
#define MBAR_BYTES  1024
#define SMEM_TOTAL  (STAGES * STAGE_BYTES + MBAR_BYTES)
/* mbar layout: full[s] at +s*8; empty[s] at +32+s*8 */

static __device__ __forceinline__ void produce_chunk(
    int cc, uint32_t smem_base, uint32_t mbar_base,
    const __half* __restrict__ gA, const __half* __restrict__ gB,
    int a_sz, int tid, uint32_t* emptyph)
{
    const int s = cc % STAGES;
    if (cc >= STAGES) {   /* first use of each stage needs no empty-wait */
        MBARRIER_WAIT_PARITY_RELAXED(mbar_base + 32 + s * 8, (*emptyph >> s) & 1);
        *emptyph ^= (1u << s);
    }
    const int row  = tid >> 1;
    const int j0   = (tid & 1) * 4;
    const uint32_t xorv = (uint32_t)(row & 7) * 16u;
    uint32_t sA = smem_base + (uint32_t)s * STAGE_BYTES + (uint32_t)row * 128u;
    uint32_t sB = sA + 16384u;
    const char* srcA = (const char*)(gA + (size_t)row * DK + (size_t)cc * KC) + j0 * 16;
    const char* srcB = (const char*)(gB + (size_t)row * DK + (size_t)cc * KC) + j0 * 16;
#pragma unroll
    for (int j = 0; j < 4; j++) {
        uint32_t col = ((uint32_t)(j0 + j) * 16u) ^ xorv;
        cp16(sA + col, srcA + j * 16, a_sz);
        cp16(sB + col, srcB + j * 16, 16);
    }
    cp_async_arrive(mbar_base + s * 8);
}

__global__ void __launch_bounds__(256, 2) gemm_kernel(
    const float* __restrict__ bias, float* __restrict__ out, int T_tokens)
{
    extern __shared__ __align__(1024) char smem[];
    const int nt = blockIdx.x;           /* fast dim: 8 N-tiles share A tile in L2 */
    const int mt = blockIdx.y;
    if (mt >= g_num_mtiles) return;

    const int e     = g_tile_expert[mt];
    const int row0  = g_tile_row[mt];
    const int nrows = g_tile_nrows[mt];

    const uint32_t smem_base = smem_u32(smem);
    const uint32_t mbar_base = smem_base + STAGES * STAGE_BYTES;
    const int tid  = threadIdx.x;
    const int lane = tid & 31;
    const int wid  = tid >> 5;
    const int warp_m = wid >> 1;         /* 0..3 */
    const int warp_n = wid & 1;          /* 0..1 */

    /* warm L2 with this CTA's bias row (512B) so the epilogue doesn't stall */
    const float* brow_base = bias + (size_t)e * DN + (size_t)nt * BN;
    if (tid < 4)
        asm volatile("prefetch.global.L2 [%0];" :: "l"(brow_base + tid * 32));

    if (tid == 0) {
#pragma unroll
        for (int s = 0; s < STAGES; s++) {
            MBARRIER_INIT(mbar_base + s * 8, 256);       /* full  */
            MBARRIER_INIT(mbar_base + 32 + s * 8, 8);    /* empty */
        }
    }
    __syncthreads();

    /* global load setup */
    const int arow = tid >> 1;
    const int a_sz = (row0 + arow < T_tokens) ? 16 : 0;
    const __half* gA = g_Ah + (size_t)row0 * DK;
    const __half* gB = g_Wh + ((size_t)e * DN + (size_t)nt * BN) * DK;

    /* ldmatrix per-lane address components */
    uint32_t aRow[2], aXor[2];
#pragma unroll
    for (int mf = 0; mf < 2; mf++) {
        int r = warp_m * 32 + mf * 16 + (lane & 15);
        aRow[mf] = (uint32_t)r * 128u;
        aXor[mf] = (uint32_t)(r & 7) * 16u;
    }
    const uint32_t aHi = (uint32_t)((lane >> 4) & 1) * 16u;

    uint32_t bRow[4], bXor[4];
#pragma unroll
    for (int g = 0; g < 4; g++) {
        int r = warp_n * 64 + g * 16 + (lane & 7) + (((lane >> 4) & 1) << 3);
        bRow[g] = (uint32_t)r * 128u;
        bXor[g] = (uint32_t)(r & 7) * 16u;
    }
    const uint32_t bHi = (uint32_t)((lane >> 3) & 1) * 16u;

    float acc[2][8][4];
#pragma unroll
    for (int mf = 0; mf < 2; mf++)
#pragma unroll
        for (int nf = 0; nf < 8; nf++)
#pragma unroll
            for (int k = 0; k < 4; k++) acc[mf][nf][k] = 0.0f;

    uint32_t fullph = 0, emptyph = 0;

    /* prologue: chunks 0 and 1 (no waits: first use of stages 0,1) */
    produce_chunk(0, smem_base, mbar_base, gA, gB, a_sz, tid, &emptyph);
    produce_chunk(1, smem_base, mbar_base, gA, gB, a_sz, tid, &emptyph);

#pragma unroll 1
    for (int c = 0; c < NCHUNK; c++) {
        const int s = c % STAGES;

        /* produce chunk c+2 (its stage was released during chunk c-1) */
        if (c + 2 < NCHUNK)
            produce_chunk(c + 2, smem_base, mbar_base, gA, gB, a_sz, tid, &emptyph);

        /* consume chunk c: per-warp wait on full[s] */
        MBARRIER_WAIT_PARITY(mbar_base + s * 8, (fullph >> s) & 1);
        fullph ^= (1u << s);

        const uint32_t sA = smem_base + (uint32_t)s * STAGE_BYTES;
        const uint32_t sB = sA + 16384u;

#pragma unroll
        for (int ks = 0; ks < 4; ks++) {
            const uint32_t kb = (uint32_t)ks * 32u;
            uint32_t a[2][4];
#pragma unroll
            for (int mf = 0; mf < 2; mf++) {
                uint32_t addr = sA + aRow[mf] + ((kb + aHi) ^ aXor[mf]);
                LDSM_X4(a[mf][0], a[mf][1], a[mf][2], a[mf][3], addr);
            }
            uint32_t b[4][4];
#pragma unroll
            for (int g = 0; g < 4; g++) {
                uint32_t addr = sB + bRow[g] + ((kb + bHi) ^ bXor[g]);
                LDSM_X4(b[g][0], b[g][1], b[g][2], b[g][3], addr);
            }

            /* after the LAST ks's LDSMs, this warp has read everything it
               will ever read from stage s -> release it before the MMAs */
            if (ks == 3 && lane == 0) MBARRIER_ARRIVE(mbar_base + 32 + s * 8);

#pragma unroll
            for (int mf = 0; mf < 2; mf++) {
#pragma unroll
                for (int nf = 0; nf < 8; nf++) {
                    const int g  = nf >> 1;
                    const int hi = (nf & 1) * 2;
                    MMA16816(acc[mf][nf][0], acc[mf][nf][1], acc[mf][nf][2], acc[mf][nf][3],
                             a[mf][0], a[mf][1], a[mf][2], a[mf][3],
                             b[g][hi], b[g][hi + 1]);
                }
            }
        }
    }

    /* epilogue: out = acc + bias (streaming stores: write-once data) */
    const int colBase = nt * BN + warp_n * 64 + (lane & 3) * 2;
    const float* brow = bias + (size_t)e * DN;
#pragma unroll
    for (int mf = 0; mf < 2; mf++) {
#pragma unroll
        for (int half = 0; half < 2; half++) {
            const int r = warp_m * 32 + mf * 16 + (lane >> 2) + half * 8;
            if (r < nrows) {
                float* orow = out + (size_t)(row0 + r) * DN;
#pragma unroll
                for (int nf = 0; nf < 8; nf++) {
                    const int col = colBase + nf * 8;
                    float vx = acc[mf][nf][half * 2 + 0] + brow[col];
                    float vy = acc[mf][nf][half * 2 + 1] + brow[col + 1];
                    STG2_CS(orow + col, vx, vy);
                }
            }
        }
    }
}

/* ---------------- host launcher ---------------- */
extern "C" void kernel_launch(void* const* d_in, const int* in_sizes, int n_in,
                              void* d_out, int out_size)
{
    const float* x    = (const float*)d_in[0];
    const int*   ef   = (const int*)d_in[1];
    const float* w    = (const float*)d_in[2];
    const float* bias = (const float*)d_in[3];
    float* out = (float*)d_out;

    const long long T = (long long)in_sizes[0] / DK;

    const long long nA16 = T * DK / 16;
    const long long nW16 = (long long)E_NUM * DN * DK / 16;
    /* 4736 bulk blocks + 1 tile-table block */
    cvt_all_kernel<<<4737, 256>>>((const float4*)w, (const float4*)x, nW16, nA16,
                                  ef, (int)T);

    cudaFuncSetAttribute(gemm_kernel, cudaFuncAttributeMaxDynamicSharedMemorySize, SMEM_TOTAL);

    const int mt_max = (int)((T + BM - 1) / BM) + E_NUM;   /* ~1056 */
    dim3 grid(DN / BN, (unsigned)mt_max);                  /* (8, ~1056) */
    gemm_kernel<<<grid, 256, SMEM_TOTAL>>>(bias, out, (int)T);
}